// round 10
// baseline (speedup 1.0000x reference)
#include <cuda_runtime.h>
#include <math.h>
#include <stdint.h>

#define NPTS    8192
#define NB      2
#define TNN     128                        // threads per NN block (4 warps)
#define NWARP   (TNN / 32)                 // 4
#define QPW     8                          // queries per WARP (uniform across lanes)
#define QPB     (NWARP * QPW)              // 32 queries per block
#define SEG     2048                       // candidate tile
#define NPAIR   (SEG / 2)                  // 1024 pairs
#define NSEG    (NPTS / SEG)               // 4
#define NQC     (NPTS / QPB)               // 256 query chunks
#define NQ_TOTAL (2 * NB * NPTS)           // 32768
#define NN_BLOCKS (2 * NB * NQC * NSEG)    // 4096
#define TLOSS   256
#define LOSS_BLOCKS (NQ_TOTAL / TLOSS)     // 128

// Scratch. g_segkeys[seg][global_q]: per-tile winner, plain stores (every slot
// rewritten each replay -> no init). Key = (order-preserving score bits << 32 |
// candidate idx): u64 min == (min score, lowest idx) == reference tie-break.
__device__ unsigned long long g_segkeys[NSEG * NQ_TOTAL];
__device__ unsigned long long g_keys[NQ_TOTAL];
__device__ int                g_counts[NQ_TOTAL];
__device__ double             g_sum;
__device__ unsigned int       g_done;

// ---- f32x2 packed FMA (sm_103a) -------------------------------------------
__device__ __forceinline__ unsigned long long ffma2(
    unsigned long long a, unsigned long long b, unsigned long long c) {
    unsigned long long d;
    asm("fma.rn.f32x2 %0, %1, %2, %3;" : "=l"(d) : "l"(a), "l"(b), "l"(c));
    return d;
}
__device__ __forceinline__ unsigned long long fdup2(float v) {
    unsigned long long r;
    asm("mov.b64 %0, {%1, %1};" : "=l"(r) : "f"(v));
    return r;
}
__device__ __forceinline__ float2 unpack2(unsigned long long v) {
    float2 r;
    asm("mov.b64 {%0, %1}, %2;" : "=f"(r.x), "=f"(r.y) : "l"(v));
    return r;
}

// ---------------------------------------------------------------------------
// Kernel 1: NN scan, broadcast-free.
// Queries: warp-uniform registers (packed -2x dups). Candidates: lane-strided
// pair-packed AoS SMEM -> conflict-free LDS.128 (full 128B/cyc, no broadcast).
// score = ||c||^2 - 2<x,c> (same argmin as squared dist). Per query: exact
// (best score, best step) tracked; j and global idx recovered bit-identically;
// cross-lane merge via u64-key butterfly (exact lowest-index tie-break).
// ---------------------------------------------------------------------------
__global__ __launch_bounds__(TNN, 5) void dacd_nn_kernel(
    const float* __restrict__ x, const float* __restrict__ gt)
{
    __shared__ __align__(16) float4 sA[NPAIR];  // (c0a,c0b,c1a,c1b) 16KB
    __shared__ __align__(16) float4 sB[NPAIR];  // (c2a,c2b,wa,wb)   16KB

    const int blk = blockIdx.x;
    const int seg = blk & (NSEG - 1);          // bits [0,2)
    const int qc  = (blk >> 2) & (NQC - 1);    // bits [2,10)
    const int b   = (blk >> 10) & 1;
    const int dir = (blk >> 11) & 1;

    // Zero counts / sum / ticket (replaces init kernel).
    if (threadIdx.x < NQ_TOTAL / NN_BLOCKS)    // 8
        g_counts[blk * (NQ_TOTAL / NN_BLOCKS) + threadIdx.x] = 0;
    if (blk == 0 && threadIdx.x == 0) { g_sum = 0.0; g_done = 0u; }

    const float* qry = dir ? gt : x;
    const float* cnd = dir ? x : gt;

    const float* c0p = cnd + (b * 3 + 0) * NPTS + seg * SEG;
    const float* c1p = cnd + (b * 3 + 1) * NPTS + seg * SEG;
    const float* c2p = cnd + (b * 3 + 2) * NPTS + seg * SEG;

    // Tile load: pair-packed AoS.
    for (int p = threadIdx.x; p < NPAIR; p += TNN) {
        float2 c0 = *(const float2*)(c0p + 2 * p);
        float2 c1 = *(const float2*)(c1p + 2 * p);
        float2 c2 = *(const float2*)(c2p + 2 * p);
        float wa = fmaf(c0.x, c0.x, fmaf(c1.x, c1.x, c2.x * c2.x));
        float wb = fmaf(c0.y, c0.y, fmaf(c1.y, c1.y, c2.y * c2.y));
        sA[p] = make_float4(c0.x, c0.y, c1.x, c1.y);
        sB[p] = make_float4(c2.x, c2.y, wa, wb);
    }
    __syncthreads();

    const int lane = threadIdx.x & 31;
    const int wid  = threadIdx.x >> 5;
    const int qbase = qc * QPB + wid * QPW;    // warp-uniform query block

    const float* qb = qry + b * 3 * NPTS;
    unsigned long long n0[QPW], n1[QPW], n2[QPW];
#pragma unroll
    for (int k = 0; k < QPW; k++) {
        int q = qbase + k;
        n0[k] = fdup2(-2.0f * qb[0 * NPTS + q]);
        n1[k] = fdup2(-2.0f * qb[1 * NPTS + q]);
        n2[k] = fdup2(-2.0f * qb[2 * NPTS + q]);
    }

    const float INF = __int_as_float(0x7f800000);
    float best[QPW];
    int   bstep[QPW];
#pragma unroll
    for (int k = 0; k < QPW; k++) { best[k] = INF; bstep[k] = 0; }

#pragma unroll 4
    for (int step = 0; step < SEG / 64; step++) {      // 32 steps
        const int idx = step * 32 + lane;              // conflict-free
        ulonglong2 va = *(const ulonglong2*)&sA[idx];  // (c0a,c0b),(c1a,c1b)
        ulonglong2 vb = *(const ulonglong2*)&sB[idx];  // (c2a,c2b),(wa,wb)
#pragma unroll
        for (int k = 0; k < QPW; k++) {
            unsigned long long t = ffma2(n2[k], vb.x, vb.y);
            t = ffma2(n1[k], va.y, t);
            t = ffma2(n0[k], va.x, t);
            float2 s = unpack2(t);
            float gm = fminf(s.x, s.y);
            bool sel = gm < best[k];       // strict: earliest step wins ties
            bstep[k] = sel ? step : bstep[k];
            best[k]  = fminf(best[k], gm);
        }
    }

    // Epilogue: recover j (even-first => lowest idx), build key, butterfly
    // min across lanes (u64 => exact lowest-global-idx tie-break), store.
    unsigned long long* segbase =
        g_segkeys + seg * NQ_TOTAL + (dir * NB + b) * NPTS;
#pragma unroll 1
    for (int k = 0; k < QPW; k++) {
        const int idx = bstep[k] * 32 + lane;
        ulonglong2 va = *(const ulonglong2*)&sA[idx];
        ulonglong2 vb = *(const ulonglong2*)&sB[idx];
        unsigned long long t = ffma2(n2[k], vb.x, vb.y);
        t = ffma2(n1[k], va.y, t);
        t = ffma2(n0[k], va.x, t);
        float2 s = unpack2(t);
        int j = (s.x <= best[k]) ? 0 : 1;
        unsigned gidx = (unsigned)(seg * SEG + bstep[k] * 64 + 2 * lane + j);
        unsigned u = __float_as_uint(best[k]);
        u ^= (u >> 31) ? 0xFFFFFFFFu : 0x80000000u;    // order-preserving
        unsigned long long key = ((unsigned long long)u << 32) | gidx;
#pragma unroll
        for (int off = 16; off > 0; off >>= 1) {
            unsigned long long o = __shfl_xor_sync(0xFFFFFFFFu, key, off);
            key = (o < key) ? o : key;
        }
        if (lane == 0) segbase[qbase + k] = key;
    }
}

// ---------------------------------------------------------------------------
// Kernel 2: per-query tile reduce (u64 min over 4 keys) + count histogram.
// ---------------------------------------------------------------------------
__global__ void dacd_reduce_count_kernel() {
    int i = blockIdx.x * blockDim.x + threadIdx.x;
    if (i >= NQ_TOTAL) return;
    unsigned long long best = g_segkeys[i];
#pragma unroll
    for (int s = 1; s < NSEG; s++) {
        unsigned long long k = g_segkeys[s * NQ_TOTAL + i];
        best = (k < best) ? k : best;
    }
    g_keys[i] = best;
    int base = i & ~(NPTS - 1);
    atomicAdd(&g_counts[base + (unsigned)(best & 0xFFFFFFFFu)], 1);
}

// ---------------------------------------------------------------------------
// Kernel 3: per-query loss + fused final reduction (ticket).
// term = 1 - exp(-10*dist)/(cnt+1e-6); dist = xx + score.
// ---------------------------------------------------------------------------
__global__ __launch_bounds__(TLOSS) void dacd_loss_kernel(
    const float* __restrict__ x, const float* __restrict__ gt,
    float* __restrict__ out)
{
    __shared__ double swarp[TLOSS / 32];

    const int i   = blockIdx.x * TLOSS + threadIdx.x;
    const int q   = i & (NPTS - 1);
    const int b   = (i >> 13) & 1;
    const int dir = (i >> 14) & 1;

    const float* qry = dir ? gt : x;

    unsigned long long key = g_keys[i];
    unsigned u = (unsigned)(key >> 32);
    unsigned orig = (u >> 31) ? (u ^ 0x80000000u) : ~u;
    float score = __uint_as_float(orig);

    float x0 = qry[(b * 3 + 0) * NPTS + q];
    float x1 = qry[(b * 3 + 1) * NPTS + q];
    float x2 = qry[(b * 3 + 2) * NPTS + q];
    float xx = fmaf(x0, x0, fmaf(x1, x1, x2 * x2));
    float dist = xx + score;

    int cnt = g_counts[(i & ~(NPTS - 1)) + (unsigned)(key & 0xFFFFFFFFu)];
    float w = 1.0f / ((float)cnt + 1e-6f);
    double v = (double)(1.0f - expf(-10.0f * dist) * w);

#pragma unroll
    for (int off = 16; off > 0; off >>= 1)
        v += __shfl_down_sync(0xFFFFFFFFu, v, off);

    int lane = threadIdx.x & 31, wid = threadIdx.x >> 5;
    if (lane == 0) swarp[wid] = v;
    __syncthreads();
    if (wid == 0) {
        v = (lane < TLOSS / 32) ? swarp[lane] : 0.0;
#pragma unroll
        for (int off = 4; off > 0; off >>= 1)
            v += __shfl_down_sync(0xFFFFFFFFu, v, off);
        if (lane == 0) {
            atomicAdd(&g_sum, v);
            __threadfence();
            unsigned t = atomicAdd(&g_done, 1u);
            if (t == LOSS_BLOCKS - 1)
                out[0] = (float)(g_sum / (double)(NPTS * 2 * NB));
        }
    }
}

extern "C" void kernel_launch(void* const* d_in, const int* in_sizes, int n_in,
                              void* d_out, int out_size) {
    const float* x  = (const float*)d_in[0];
    const float* gt = (const float*)d_in[1];
    float* out = (float*)d_out;

    dacd_nn_kernel<<<NN_BLOCKS, TNN>>>(x, gt);
    dacd_reduce_count_kernel<<<(NQ_TOTAL + 255) / 256, 256>>>();
    dacd_loss_kernel<<<LOSS_BLOCKS, TLOSS>>>(x, gt, out);
}